// round 13
// baseline (speedup 1.0000x reference)
#include <cuda_runtime.h>
#include <cuda_bf16.h>
#include <math.h>
#include <stdint.h>

#define B 4096
#define D 256
#define MARGIN 0.3f
#define NTHREADS 512
#define BK 64            // tf32 K elems per stage
#define NSTAGE 4         // D / BK
#define NBUF 3
#define STRIDE 272       // 256B data + 16B pad (17 segs, odd -> conflict-free)
#define TILE_BYTES (128 * STRIDE)        // 34816 per matrix
#define STAGE_BYTES (2 * TILE_BYTES)     // A | B = 69632
#define SMEM_RED (NBUF * STAGE_BYTES)    // 208896
#define SMEM_TOTAL (SMEM_RED + 4096)     // 212992 < 227KB cap
#define NTILE 32                         // B / 128
#define NTRI (NTILE * (NTILE + 1) / 2)   // 528

// ---- device scratch ----
__device__ int   g_hp_bits[B];
__device__ int   g_hn_bits[B];
__device__ int   g_lab[B];
__device__ int   g_cnt[64];
__device__ float g_sum;
__device__ float g_vcnt;
__device__ unsigned int g_done;

// ---------------------------------------------------------------------------
// PTX helpers (sm_80+ family-safe)
// ---------------------------------------------------------------------------
__device__ __forceinline__ void cp16(uint32_t s, const void* g) {
    asm volatile("cp.async.cg.shared.global [%0], [%1], 16;" :: "r"(s), "l"(g));
}
__device__ __forceinline__ void cp_commit() {
    asm volatile("cp.async.commit_group;");
}
template <int N>
__device__ __forceinline__ void cp_wait() {
    asm volatile("cp.async.wait_group %0;" :: "n"(N));
}
__device__ __forceinline__ void ldm4(uint32_t* r, uint32_t addr) {
    asm volatile("ldmatrix.sync.aligned.m8n8.x4.shared.b16 {%0,%1,%2,%3}, [%4];"
                 : "=r"(r[0]), "=r"(r[1]), "=r"(r[2]), "=r"(r[3]) : "r"(addr));
}
__device__ __forceinline__ void lds4(float4& v, uint32_t addr) {
    asm volatile("ld.shared.v4.f32 {%0,%1,%2,%3}, [%4];"
                 : "=f"(v.x), "=f"(v.y), "=f"(v.z), "=f"(v.w) : "r"(addr));
}
__device__ __forceinline__ void mma_tf32(float* c, const uint32_t* a,
                                         uint32_t b0, uint32_t b1) {
    asm volatile(
        "mma.sync.aligned.m16n8k8.row.col.f32.tf32.tf32.f32 "
        "{%0,%1,%2,%3}, {%4,%5,%6,%7}, {%8,%9}, {%0,%1,%2,%3};"
        : "+f"(c[0]), "+f"(c[1]), "+f"(c[2]), "+f"(c[3])
        : "r"(a[0]), "r"(a[1]), "r"(a[2]), "r"(a[3]), "r"(b0), "r"(b1));
}
// tf32 truncation mask: exactly the bits the tensor core keeps from fp32
__device__ __forceinline__ float tf32_trunc(float x) {
    return __uint_as_float(__float_as_uint(x) & 0xFFFFE000u);
}

// ---------------------------------------------------------------------------
// k_labels: single block — dtype detect + normalize + histogram + init
// ---------------------------------------------------------------------------
__global__ __launch_bounds__(256) void k_labels(const int* __restrict__ raw) {
    const int tid = threadIdx.x;
    __shared__ int s_any;
    __shared__ int s_hist[64];
    if (tid == 0) { s_any = 0; g_done = 0u; g_sum = 0.f; g_vcnt = 0.f; }
    if (tid < 64) s_hist[tid] = 0;
    __syncthreads();
    int local = 0;
    const int4* r4 = (const int4*)raw;   // odd words within first 16KB (safe)
    for (int t = tid; t < 1024; t += 256) {
        int4 v = r4[t];
        if ((v.y | v.w) != 0) local = 1;
    }
    if (local) atomicOr(&s_any, 1);
    __syncthreads();
    const bool is_i32 = (s_any != 0);
    for (int i = tid; i < B; i += 256) {
        int l = is_i32 ? raw[i] : raw[2 * i];
        g_lab[i] = l;
        atomicAdd(&s_hist[l & 63], 1);
        g_hp_bits[i] = 0;
        g_hn_bits[i] = 0x7F7FFFFF;
    }
    __syncthreads();
    if (tid < 64) g_cnt[tid] = s_hist[tid];
}

// ---------------------------------------------------------------------------
// k_gemm: triangular tiles, 16 warps, warp tile 32x32, TF32 m16n8k8
// direct from fp32 E; per-row sq computed IN-KERNEL from smem with the
// tf32 truncation mask (consistent with what the MMA consumes).
// ---------------------------------------------------------------------------
__device__ __forceinline__ void issue_stage(const float* __restrict__ E,
                                            uint32_t sbase, int i0, int j0,
                                            int s, int tid) {
    const int k0 = s * BK;
    #pragma unroll
    for (int m = 0; m < 8; m++) {
        int task = m * NTHREADS + tid;          // 0..4095
        int mat = task >> 11;                   // 0 = A, 1 = B
        int idx = task & 2047;
        int row = idx >> 4;
        int q = idx & 15;
        int grow = (mat == 0 ? i0 : j0) + row;
        const float* src = E + (size_t)grow * D + k0 + q * 4;
        uint32_t dst = sbase + mat * TILE_BYTES + row * STRIDE + q * 16;
        cp16(dst, src);
    }
}

__global__ __launch_bounds__(NTHREADS, 1) void k_gemm(const float* __restrict__ E) {
    extern __shared__ char smem[];
    const int tid = threadIdx.x;
    const int lane = tid & 31;
    const int wid = tid >> 5;
    const int wm = wid >> 2;       // 0..3
    const int wn = wid & 3;        // 0..3

    int t = blockIdx.x;
    int bi = 0;
    while (t >= NTILE - bi) { t -= NTILE - bi; bi++; }
    const int bj = bi + t;
    const bool diag = (bi == bj);
    const int i0 = bi * 128;
    const int j0 = bj * 128;

    const uint32_t sb = (uint32_t)__cvta_generic_to_shared(smem);
    int* s_hp = (int*)(smem + SMEM_RED);
    int* s_hn = s_hp + 128;
    int* s_hp2 = s_hn + 128;
    int* s_hn2 = s_hp2 + 128;
    float* s_sq = (float*)(s_hn2 + 128);   // [256]: A rows 0..127, B rows 128..255

    if (tid < 128) {
        s_hp[tid] = 0;  s_hn[tid] = 0x7F7FFFFF;
        s_hp2[tid] = 0; s_hn2[tid] = 0x7F7FFFFF;
    }

    float acc[2][4][4];
    #pragma unroll
    for (int a = 0; a < 2; a++)
        #pragma unroll
        for (int b = 0; b < 4; b++)
            #pragma unroll
            for (int c = 0; c < 4; c++)
                acc[a][b][c] = 0.f;

    const uint32_t aoff = (uint32_t)((wm * 32 + ((lane >> 3) & 1) * 8 + (lane & 7)) * STRIDE
                                     + (lane >> 4) * 16);
    const uint32_t boff = (uint32_t)((wn * 32 + ((lane >> 4) & 1) * 8 + (lane & 7)) * STRIDE
                                     + ((lane >> 3) & 1) * 16);

    // sq-accumulation assignment: 2 threads per row (256 rows: A then B)
    const int r256 = tid >> 1;
    const uint32_t sqoff = (uint32_t)((r256 < 128 ? r256 * STRIDE
                                       : TILE_BYTES + (r256 - 128) * STRIDE)
                                      + (tid & 1) * 128);
    float sqacc = 0.f;

    issue_stage(E, sb, i0, j0, 0, tid);
    cp_commit();
    issue_stage(E, sb + STAGE_BYTES, i0, j0, 1, tid);
    cp_commit();

    #pragma unroll
    for (int s = 0; s < NSTAGE; s++) {
        if (s < NSTAGE - 1) cp_wait<1>(); else cp_wait<0>();
        __syncthreads();
        if (s + 2 < NSTAGE) {
            issue_stage(E, sb + ((s + 2) % NBUF) * STAGE_BYTES, i0, j0, s + 2, tid);
            cp_commit();
        }

        const uint32_t st = sb + (s % NBUF) * STAGE_BYTES;

        // per-row squared-norm partials on tf32-truncated values
        {
            const uint32_t rb = st + sqoff;
            #pragma unroll
            for (int q = 0; q < 8; q++) {
                float4 v;
                lds4(v, rb + q * 16);
                float x0 = tf32_trunc(v.x), x1 = tf32_trunc(v.y);
                float x2 = tf32_trunc(v.z), x3 = tf32_trunc(v.w);
                sqacc = fmaf(x0, x0, sqacc);
                sqacc = fmaf(x1, x1, sqacc);
                sqacc = fmaf(x2, x2, sqacc);
                sqacc = fmaf(x3, x3, sqacc);
            }
        }

        const uint32_t Abase = st + aoff;
        const uint32_t Bbase = st + TILE_BYTES + boff;

        #pragma unroll
        for (int kk = 0; kk < 2; kk++) {
            #pragma unroll
            for (int h = 0; h < 4; h++) {
                const uint32_t kb = (uint32_t)(kk * 128 + h * 32);
                uint32_t a[2][4], b[2][4];
                #pragma unroll
                for (int mi = 0; mi < 2; mi++)
                    ldm4(a[mi], Abase + mi * 16 * STRIDE + kb);
                #pragma unroll
                for (int p = 0; p < 2; p++)
                    ldm4(b[p], Bbase + p * 16 * STRIDE + kb);
                #pragma unroll
                for (int mi = 0; mi < 2; mi++) {
                    #pragma unroll
                    for (int ni = 0; ni < 4; ni++) {
                        const int p = ni >> 1, o = (ni & 1) * 2;
                        mma_tf32(acc[mi][ni], a[mi], b[p][o], b[p][o + 1]);
                    }
                }
            }
        }
    }

    // combine the two per-row halves and publish sq
    sqacc += __shfl_xor_sync(0xFFFFFFFFu, sqacc, 1);
    if ((tid & 1) == 0) s_sq[r256] = sqacc;
    __syncthreads();

    // ---- epilogue ----
    int lj[8], gjs[8];
    float sqj[8];
    #pragma unroll
    for (int idx = 0; idx < 8; idx++) {
        const int ni = idx >> 1, c = idx & 1;
        const int cloc = wn * 32 + ni * 8 + (lane & 3) * 2 + c;
        gjs[idx] = j0 + cloc;
        lj[idx] = g_lab[j0 + cloc];
        sqj[idx] = s_sq[128 + cloc];
    }

    float chp[8], chn[8];
    #pragma unroll
    for (int idx = 0; idx < 8; idx++) { chp[idx] = 0.f; chn[idx] = 3.4e38f; }

    #pragma unroll
    for (int mi = 0; mi < 2; mi++) {
        #pragma unroll
        for (int h = 0; h < 2; h++) {
            const int rloc = wm * 32 + mi * 16 + h * 8 + (lane >> 2);
            const int gi = i0 + rloc;
            const int li = g_lab[gi];
            const float sqi = s_sq[rloc];
            float hp = 0.f, hn = 3.4e38f;
            #pragma unroll
            for (int ni = 0; ni < 4; ni++) {
                #pragma unroll
                for (int c = 0; c < 2; c++) {
                    const int idx = ni * 2 + c;
                    float d2 = fmaf(-2.f, acc[mi][ni][h * 2 + c], sqi + sqj[idx]);
                    const bool same = (lj[idx] == li);
                    const bool self = (gjs[idx] == gi);
                    if (same) {
                        if (!self) {
                            hp = fmaxf(hp, d2);
                            chp[idx] = fmaxf(chp[idx], d2);
                        }
                    } else {
                        hn = fminf(hn, d2);
                        chn[idx] = fminf(chn[idx], d2);
                    }
                }
            }
            hp = fmaxf(hp, __shfl_xor_sync(0xFFFFFFFFu, hp, 1));
            hn = fminf(hn, __shfl_xor_sync(0xFFFFFFFFu, hn, 1));
            hp = fmaxf(hp, __shfl_xor_sync(0xFFFFFFFFu, hp, 2));
            hn = fminf(hn, __shfl_xor_sync(0xFFFFFFFFu, hn, 2));
            if ((lane & 3) == 0) {
                atomicMax(&s_hp[rloc], __float_as_int(hp));
                atomicMin(&s_hn[rloc], __float_as_int(hn));
            }
        }
    }

    if (!diag) {
        #pragma unroll
        for (int idx = 0; idx < 8; idx++) {
            float vp = chp[idx], vn = chn[idx];
            #pragma unroll
            for (int m = 4; m < 32; m <<= 1) {
                vp = fmaxf(vp, __shfl_xor_sync(0xFFFFFFFFu, vp, m));
                vn = fminf(vn, __shfl_xor_sync(0xFFFFFFFFu, vn, m));
            }
            if ((lane >> 2) == 0) {
                const int ni = idx >> 1, c = idx & 1;
                const int cloc = wn * 32 + ni * 8 + (lane & 3) * 2 + c;
                atomicMax(&s_hp2[cloc], __float_as_int(vp));
                atomicMin(&s_hn2[cloc], __float_as_int(vn));
            }
        }
    }

    __syncthreads();
    if (tid < 128) {
        atomicMax(&g_hp_bits[i0 + tid], s_hp[tid]);
        atomicMin(&g_hn_bits[i0 + tid], s_hn[tid]);
        if (!diag) {
            atomicMax(&g_hp_bits[j0 + tid], s_hp2[tid]);
            atomicMin(&g_hn_bits[j0 + tid], s_hn2[tid]);
        }
    }
}

// ---------------------------------------------------------------------------
// k_final: partial blocks -> atomics; last block writes out.
// ---------------------------------------------------------------------------
__global__ __launch_bounds__(256) void k_final(float* __restrict__ out) {
    const int i = blockIdx.x * 256 + threadIdx.x;
    const int tid = threadIdx.x;
    float sum = 0.f, cnt = 0.f;
    const int c = g_cnt[g_lab[i] & 63];
    if (c >= 2 && c <= B - 1) {
        float hp = sqrtf(fmaxf(__int_as_float(g_hp_bits[i]), 0.f));
        float hn = sqrtf(fmaxf(__int_as_float(g_hn_bits[i]), 0.f));
        float l = hp - hn + MARGIN;
        if (l > 0.f) sum = l;
        cnt = 1.f;
    }
    #pragma unroll
    for (int m = 16; m > 0; m >>= 1) {
        sum += __shfl_xor_sync(0xFFFFFFFFu, sum, m);
        cnt += __shfl_xor_sync(0xFFFFFFFFu, cnt, m);
    }
    __shared__ float ss[8], sc[8];
    __shared__ bool is_last;
    if ((tid & 31) == 0) { ss[tid >> 5] = sum; sc[tid >> 5] = cnt; }
    __syncthreads();
    if (tid == 0) {
        float S = 0.f, C = 0.f;
        #pragma unroll
        for (int w = 0; w < 8; w++) { S += ss[w]; C += sc[w]; }
        atomicAdd(&g_sum, S);
        atomicAdd(&g_vcnt, C);
        __threadfence();
        unsigned int n = atomicAdd(&g_done, 1u);
        is_last = (n == gridDim.x - 1);
    }
    __syncthreads();
    if (is_last && tid == 0) {
        float cfin = *((volatile float*)&g_vcnt);
        float sfin = *((volatile float*)&g_sum);
        out[0] = (cfin > 0.f) ? (sfin / cfin) : 0.f;
    }
}

// ---------------------------------------------------------------------------
extern "C" void kernel_launch(void* const* d_in, const int* in_sizes, int n_in,
                              void* d_out, int out_size) {
    const float* E = (const float*)d_in[0];
    const int* labels_raw = (const int*)d_in[1];
    float* out = (float*)d_out;

    static bool attr_set = false;
    if (!attr_set) {
        cudaFuncSetAttribute(k_gemm, cudaFuncAttributeMaxDynamicSharedMemorySize,
                             SMEM_TOTAL);
        attr_set = true;
    }

    k_labels<<<1, 256>>>(labels_raw);
    k_gemm<<<NTRI, NTHREADS, SMEM_TOTAL>>>(E);
    k_final<<<B / 256, 256>>>(out);
}

// round 14
// speedup vs baseline: 1.0168x; 1.0168x over previous
#include <cuda_runtime.h>
#include <cuda_bf16.h>
#include <math.h>
#include <stdint.h>

#define B 4096
#define D 256
#define MARGIN 0.3f
#define NTHREADS 512
#define BK 64            // tf32 K elems per stage
#define NSTAGE 4         // D / BK
#define NBUF 3
#define STRIDE 272       // 256B data + 16B pad (17 segs, odd -> conflict-free)
#define TILE_BYTES (128 * STRIDE)        // 34816 per matrix
#define STAGE_BYTES (2 * TILE_BYTES)     // A | B = 69632
#define SMEM_RED (NBUF * STAGE_BYTES)    // 208896
#define SMEM_TOTAL (SMEM_RED + 2048)     // 210944 < 227KB cap
#define NTILE 32                         // B / 128
#define NTRI (NTILE * (NTILE + 1) / 2)   // 528

// ---- device scratch ----
__device__ int   g_hp_bits[B];
__device__ int   g_hn_bits[B];
__device__ float g_sq[B];
__device__ int   g_lab[B];
__device__ int   g_cnt[64];
__device__ unsigned int g_done;
__device__ float g_Etf[B * D];           // rna-rounded tf32 embeddings

// ---------------------------------------------------------------------------
// PTX helpers (sm_80+ family-safe)
// ---------------------------------------------------------------------------
__device__ __forceinline__ void cp16(uint32_t s, const void* g) {
    asm volatile("cp.async.cg.shared.global [%0], [%1], 16;" :: "r"(s), "l"(g));
}
__device__ __forceinline__ void cp_commit() {
    asm volatile("cp.async.commit_group;");
}
template <int N>
__device__ __forceinline__ void cp_wait() {
    asm volatile("cp.async.wait_group %0;" :: "n"(N));
}
__device__ __forceinline__ void ldm4(uint32_t* r, uint32_t addr) {
    asm volatile("ldmatrix.sync.aligned.m8n8.x4.shared.b16 {%0,%1,%2,%3}, [%4];"
                 : "=r"(r[0]), "=r"(r[1]), "=r"(r[2]), "=r"(r[3]) : "r"(addr));
}
__device__ __forceinline__ void mma_tf32(float* c, const uint32_t* a,
                                         uint32_t b0, uint32_t b1) {
    asm volatile(
        "mma.sync.aligned.m16n8k8.row.col.f32.tf32.tf32.f32 "
        "{%0,%1,%2,%3}, {%4,%5,%6,%7}, {%8,%9}, {%0,%1,%2,%3};"
        : "+f"(c[0]), "+f"(c[1]), "+f"(c[2]), "+f"(c[3])
        : "r"(a[0]), "r"(a[1]), "r"(a[2]), "r"(a[3]), "r"(b0), "r"(b1));
}
__device__ __forceinline__ uint32_t cvt_tf32(float x) {
    uint32_t r;
    asm("cvt.rna.tf32.f32 %0, %1;" : "=r"(r) : "f"(x));
    return r;
}

// ---------------------------------------------------------------------------
// k_prep: block 0 = labels + init (concurrent with staging blocks);
//         blocks 1..128 = rna-round to tf32 + row norms on rounded values.
//         Each warp owns 4 rows; all 8 LDG.128 issued up front (MLP=8).
// ---------------------------------------------------------------------------
__global__ __launch_bounds__(256) void k_prep(const float* __restrict__ E,
                                              const int* __restrict__ raw) {
    const int tid = threadIdx.x;
    if (blockIdx.x == 0) {
        __shared__ int s_any;
        __shared__ int s_hist[64];
        if (tid == 0) { s_any = 0; g_done = 0u; }
        if (tid < 64) s_hist[tid] = 0;
        __syncthreads();
        int local = 0;
        const int4* r4 = (const int4*)raw;   // odd words within first 16KB (safe)
        for (int t = tid; t < 1024; t += 256) {
            int4 v = r4[t];
            if ((v.y | v.w) != 0) local = 1;
        }
        if (local) atomicOr(&s_any, 1);
        __syncthreads();
        const bool is_i32 = (s_any != 0);
        for (int i = tid; i < B; i += 256) {
            int l = is_i32 ? raw[i] : raw[2 * i];
            g_lab[i] = l;
            atomicAdd(&s_hist[l & 63], 1);
            g_hp_bits[i] = 0;
            g_hn_bits[i] = 0x7F7FFFFF;
        }
        __syncthreads();
        if (tid < 64) g_cnt[tid] = s_hist[tid];
        return;
    }

    const int wslot = (blockIdx.x - 1) * 8 + (tid >> 5);   // 0..1023
    const int lane = tid & 31;
    const int row0 = wslot * 4;

    float4 va[4], vb[4];
    #pragma unroll
    for (int r = 0; r < 4; r++) {
        const float4* e = (const float4*)(E + (size_t)(row0 + r) * D);
        va[r] = e[2 * lane];
        vb[r] = e[2 * lane + 1];
    }
    #pragma unroll
    for (int r = 0; r < 4; r++) {
        uint4 ta, tb;
        ta.x = cvt_tf32(va[r].x); ta.y = cvt_tf32(va[r].y);
        ta.z = cvt_tf32(va[r].z); ta.w = cvt_tf32(va[r].w);
        tb.x = cvt_tf32(vb[r].x); tb.y = cvt_tf32(vb[r].y);
        tb.z = cvt_tf32(vb[r].z); tb.w = cvt_tf32(vb[r].w);

        float s = 0.f;
        const uint32_t* u = (const uint32_t*)&ta;
        const uint32_t* v = (const uint32_t*)&tb;
        #pragma unroll
        for (int q = 0; q < 4; q++) {
            float x = __uint_as_float(u[q]);
            float y = __uint_as_float(v[q]);
            s = fmaf(x, x, s);
            s = fmaf(y, y, s);
        }

        uint4* dst = (uint4*)(g_Etf + (size_t)(row0 + r) * D);
        dst[2 * lane] = ta;
        dst[2 * lane + 1] = tb;

        #pragma unroll
        for (int off = 16; off > 0; off >>= 1)
            s += __shfl_xor_sync(0xFFFFFFFFu, s, off);
        if (lane == 0) g_sq[row0 + r] = s;
    }
}

// ---------------------------------------------------------------------------
// k_gemm: 529 blocks. Blocks 0..527 = triangular TF32 tiles (R11 body).
//         Block 528 = finale: spin on done-counter, then mean reduction.
// ---------------------------------------------------------------------------
__device__ __forceinline__ void issue_stage(uint32_t sbase, int i0, int j0,
                                            int s, int tid) {
    const int k0 = s * BK;
    #pragma unroll
    for (int m = 0; m < 8; m++) {
        int task = m * NTHREADS + tid;          // 0..4095
        int mat = task >> 11;                   // 0 = A, 1 = B
        int idx = task & 2047;
        int row = idx >> 4;
        int q = idx & 15;
        int grow = (mat == 0 ? i0 : j0) + row;
        const float* src = g_Etf + (size_t)grow * D + k0 + q * 4;
        uint32_t dst = sbase + mat * TILE_BYTES + row * STRIDE + q * 16;
        cp16(dst, src);
    }
}

__global__ __launch_bounds__(NTHREADS, 1) void k_gemm(float* __restrict__ out) {
    extern __shared__ char smem[];
    const int tid = threadIdx.x;

    // ---- finale block: disjoint early path (keeps gemm regs unaffected) ----
    if (blockIdx.x == NTRI) {
        if (tid == 0) {
            while (atomicAdd(&g_done, 0u) < NTRI) __nanosleep(200);
        }
        __syncthreads();
        __threadfence();
        float sum = 0.f, cnt = 0.f;
        #pragma unroll
        for (int it = 0; it < B / NTHREADS; it++) {
            const int i = it * NTHREADS + tid;
            const int c = g_cnt[g_lab[i] & 63];
            if (c >= 2 && c <= B - 1) {
                float hp = sqrtf(fmaxf(__int_as_float(g_hp_bits[i]), 0.f));
                float hn = sqrtf(fmaxf(__int_as_float(g_hn_bits[i]), 0.f));
                float l = hp - hn + MARGIN;
                if (l > 0.f) sum += l;
                cnt += 1.f;
            }
        }
        #pragma unroll
        for (int m = 16; m > 0; m >>= 1) {
            sum += __shfl_xor_sync(0xFFFFFFFFu, sum, m);
            cnt += __shfl_xor_sync(0xFFFFFFFFu, cnt, m);
        }
        float* fs = (float*)smem;
        float* fc = fs + 16;
        if ((tid & 31) == 0) { fs[tid >> 5] = sum; fc[tid >> 5] = cnt; }
        __syncthreads();
        if (tid == 0) {
            float S = 0.f, C = 0.f;
            #pragma unroll
            for (int w = 0; w < 16; w++) { S += fs[w]; C += fc[w]; }
            out[0] = (C > 0.f) ? (S / C) : 0.f;
        }
        return;
    }

    const int lane = tid & 31;
    const int wid = tid >> 5;
    const int wm = wid >> 2;       // 0..3
    const int wn = wid & 3;        // 0..3

    int t = blockIdx.x;
    int bi = 0;
    while (t >= NTILE - bi) { t -= NTILE - bi; bi++; }
    const int bj = bi + t;
    const bool diag = (bi == bj);
    const int i0 = bi * 128;
    const int j0 = bj * 128;

    const uint32_t sb = (uint32_t)__cvta_generic_to_shared(smem);
    int* s_hp = (int*)(smem + SMEM_RED);
    int* s_hn = s_hp + 128;
    int* s_hp2 = s_hn + 128;
    int* s_hn2 = s_hp2 + 128;

    if (tid < 128) {
        s_hp[tid] = 0;  s_hn[tid] = 0x7F7FFFFF;
        s_hp2[tid] = 0; s_hn2[tid] = 0x7F7FFFFF;
    }

    float acc[2][4][4];
    #pragma unroll
    for (int a = 0; a < 2; a++)
        #pragma unroll
        for (int b = 0; b < 4; b++)
            #pragma unroll
            for (int c = 0; c < 4; c++)
                acc[a][b][c] = 0.f;

    const uint32_t aoff = (uint32_t)((wm * 32 + ((lane >> 3) & 1) * 8 + (lane & 7)) * STRIDE
                                     + (lane >> 4) * 16);
    const uint32_t boff = (uint32_t)((wn * 32 + ((lane >> 4) & 1) * 8 + (lane & 7)) * STRIDE
                                     + ((lane >> 3) & 1) * 16);

    issue_stage(sb, i0, j0, 0, tid);
    cp_commit();
    issue_stage(sb + STAGE_BYTES, i0, j0, 1, tid);
    cp_commit();

    #pragma unroll
    for (int s = 0; s < NSTAGE; s++) {
        if (s < NSTAGE - 1) cp_wait<1>(); else cp_wait<0>();
        __syncthreads();
        if (s + 2 < NSTAGE) {
            issue_stage(sb + ((s + 2) % NBUF) * STAGE_BYTES, i0, j0, s + 2, tid);
            cp_commit();
        }

        const uint32_t Abase = sb + (s % NBUF) * STAGE_BYTES + aoff;
        const uint32_t Bbase = sb + (s % NBUF) * STAGE_BYTES + TILE_BYTES + boff;

        #pragma unroll
        for (int kk = 0; kk < 2; kk++) {
            #pragma unroll
            for (int h = 0; h < 4; h++) {
                const uint32_t kb = (uint32_t)(kk * 128 + h * 32);
                uint32_t a[2][4], b[2][4];
                #pragma unroll
                for (int mi = 0; mi < 2; mi++)
                    ldm4(a[mi], Abase + mi * 16 * STRIDE + kb);
                #pragma unroll
                for (int p = 0; p < 2; p++)
                    ldm4(b[p], Bbase + p * 16 * STRIDE + kb);
                #pragma unroll
                for (int mi = 0; mi < 2; mi++) {
                    #pragma unroll
                    for (int ni = 0; ni < 4; ni++) {
                        const int p = ni >> 1, o = (ni & 1) * 2;
                        mma_tf32(acc[mi][ni], a[mi], b[p][o], b[p][o + 1]);
                    }
                }
            }
        }
    }
    __syncthreads();

    // ---- epilogue ----
    int lj[8], gjs[8];
    float sqj[8];
    #pragma unroll
    for (int idx = 0; idx < 8; idx++) {
        const int ni = idx >> 1, c = idx & 1;
        const int gj = j0 + wn * 32 + ni * 8 + (lane & 3) * 2 + c;
        gjs[idx] = gj;
        lj[idx] = g_lab[gj];
        sqj[idx] = g_sq[gj];
    }

    float chp[8], chn[8];
    #pragma unroll
    for (int idx = 0; idx < 8; idx++) { chp[idx] = 0.f; chn[idx] = 3.4e38f; }

    #pragma unroll
    for (int mi = 0; mi < 2; mi++) {
        #pragma unroll
        for (int h = 0; h < 2; h++) {
            const int rloc = wm * 32 + mi * 16 + h * 8 + (lane >> 2);
            const int gi = i0 + rloc;
            const int li = g_lab[gi];
            const float sqi = g_sq[gi];
            float hp = 0.f, hn = 3.4e38f;
            #pragma unroll
            for (int ni = 0; ni < 4; ni++) {
                #pragma unroll
                for (int c = 0; c < 2; c++) {
                    const int idx = ni * 2 + c;
                    float d2 = fmaf(-2.f, acc[mi][ni][h * 2 + c], sqi + sqj[idx]);
                    const bool same = (lj[idx] == li);
                    const bool self = (gjs[idx] == gi);
                    if (same) {
                        if (!self) {
                            hp = fmaxf(hp, d2);
                            chp[idx] = fmaxf(chp[idx], d2);
                        }
                    } else {
                        hn = fminf(hn, d2);
                        chn[idx] = fminf(chn[idx], d2);
                    }
                }
            }
            hp = fmaxf(hp, __shfl_xor_sync(0xFFFFFFFFu, hp, 1));
            hn = fminf(hn, __shfl_xor_sync(0xFFFFFFFFu, hn, 1));
            hp = fmaxf(hp, __shfl_xor_sync(0xFFFFFFFFu, hp, 2));
            hn = fminf(hn, __shfl_xor_sync(0xFFFFFFFFu, hn, 2));
            if ((lane & 3) == 0) {
                atomicMax(&s_hp[rloc], __float_as_int(hp));
                atomicMin(&s_hn[rloc], __float_as_int(hn));
            }
        }
    }

    if (!diag) {
        #pragma unroll
        for (int idx = 0; idx < 8; idx++) {
            float vp = chp[idx], vn = chn[idx];
            #pragma unroll
            for (int m = 4; m < 32; m <<= 1) {
                vp = fmaxf(vp, __shfl_xor_sync(0xFFFFFFFFu, vp, m));
                vn = fminf(vn, __shfl_xor_sync(0xFFFFFFFFu, vn, m));
            }
            if ((lane >> 2) == 0) {
                const int ni = idx >> 1, c = idx & 1;
                const int cloc = wn * 32 + ni * 8 + (lane & 3) * 2 + c;
                atomicMax(&s_hp2[cloc], __float_as_int(vp));
                atomicMin(&s_hn2[cloc], __float_as_int(vn));
            }
        }
    }

    __syncthreads();
    if (tid < 128) {
        atomicMax(&g_hp_bits[i0 + tid], s_hp[tid]);
        atomicMin(&g_hn_bits[i0 + tid], s_hn[tid]);
        if (!diag) {
            atomicMax(&g_hp_bits[j0 + tid], s_hp2[tid]);
            atomicMin(&g_hn_bits[j0 + tid], s_hn2[tid]);
        }
    }
    __syncthreads();
    if (tid == 0) {
        __threadfence();
        atomicAdd(&g_done, 1u);
    }
}

// ---------------------------------------------------------------------------
extern "C" void kernel_launch(void* const* d_in, const int* in_sizes, int n_in,
                              void* d_out, int out_size) {
    const float* E = (const float*)d_in[0];
    const int* labels_raw = (const int*)d_in[1];
    float* out = (float*)d_out;

    static bool attr_set = false;
    if (!attr_set) {
        cudaFuncSetAttribute(k_gemm, cudaFuncAttributeMaxDynamicSharedMemorySize,
                             SMEM_TOTAL);
        attr_set = true;
    }

    k_prep<<<129, 256>>>(E, labels_raw);
    k_gemm<<<NTRI + 1, NTHREADS, SMEM_TOTAL>>>(out);
}

// round 15
// speedup vs baseline: 1.1642x; 1.1449x over previous
#include <cuda_runtime.h>
#include <cuda_bf16.h>
#include <math.h>
#include <stdint.h>

#define B 4096
#define D 256
#define MARGIN 0.3f
#define NTHREADS 512
#define BK 64            // tf32 K elems per stage
#define NSTAGE 4         // D / BK
#define NBUF 3
#define STRIDE 272       // 256B data + 16B pad (17 segs, odd -> conflict-free)
#define TILE_BYTES (128 * STRIDE)        // 34816 per matrix
#define STAGE_BYTES (2 * TILE_BYTES)     // A | B = 69632
#define SMEM_RED (NBUF * STAGE_BYTES)    // 208896
#define SMEM_TOTAL (SMEM_RED + 2048)     // 210944 < 227KB cap
#define NTILE 32                         // B / 128
#define NTRI (NTILE * (NTILE + 1) / 2)   // 528

// ---- device scratch ----
__device__ int   g_hp_bits[B];
__device__ int   g_hn_bits[B];
__device__ float g_sq[B];
__device__ int   g_lab[B];
__device__ int   g_cnt[64];
__device__ float g_sum;
__device__ float g_vcnt;
__device__ unsigned int g_done;
__device__ float g_Etf[B * D];           // rna-rounded tf32 embeddings

// ---------------------------------------------------------------------------
// PTX helpers (sm_80+ family-safe)
// ---------------------------------------------------------------------------
__device__ __forceinline__ void cp16(uint32_t s, const void* g) {
    asm volatile("cp.async.cg.shared.global [%0], [%1], 16;" :: "r"(s), "l"(g));
}
__device__ __forceinline__ void cp_commit() {
    asm volatile("cp.async.commit_group;");
}
template <int N>
__device__ __forceinline__ void cp_wait() {
    asm volatile("cp.async.wait_group %0;" :: "n"(N));
}
__device__ __forceinline__ void ldm4(uint32_t* r, uint32_t addr) {
    asm volatile("ldmatrix.sync.aligned.m8n8.x4.shared.b16 {%0,%1,%2,%3}, [%4];"
                 : "=r"(r[0]), "=r"(r[1]), "=r"(r[2]), "=r"(r[3]) : "r"(addr));
}
__device__ __forceinline__ void mma_tf32(float* c, const uint32_t* a,
                                         uint32_t b0, uint32_t b1) {
    asm volatile(
        "mma.sync.aligned.m16n8k8.row.col.f32.tf32.tf32.f32 "
        "{%0,%1,%2,%3}, {%4,%5,%6,%7}, {%8,%9}, {%0,%1,%2,%3};"
        : "+f"(c[0]), "+f"(c[1]), "+f"(c[2]), "+f"(c[3])
        : "r"(a[0]), "r"(a[1]), "r"(a[2]), "r"(a[3]), "r"(b0), "r"(b1));
}
__device__ __forceinline__ uint32_t cvt_tf32(float x) {
    uint32_t r;
    asm("cvt.rna.tf32.f32 %0, %1;" : "=r"(r) : "f"(x));
    return r;
}

// ---------------------------------------------------------------------------
// k_prep: block 0 = labels + accumulator init (runs concurrently);
//         blocks 1..128 = rna-round to tf32 + row norms, 4 rows/warp, MLP=8.
// ---------------------------------------------------------------------------
__global__ __launch_bounds__(256) void k_prep(const float* __restrict__ E,
                                              const int* __restrict__ raw) {
    const int tid = threadIdx.x;
    if (blockIdx.x == 0) {
        __shared__ int s_any;
        __shared__ int s_hist[64];
        if (tid == 0) { s_any = 0; g_done = 0u; g_sum = 0.f; g_vcnt = 0.f; }
        if (tid < 64) s_hist[tid] = 0;
        __syncthreads();
        int local = 0;
        const int4* r4 = (const int4*)raw;   // odd words within first 16KB (safe)
        for (int t = tid; t < 1024; t += 256) {
            int4 v = r4[t];
            if ((v.y | v.w) != 0) local = 1;
        }
        if (local) atomicOr(&s_any, 1);
        __syncthreads();
        const bool is_i32 = (s_any != 0);
        for (int i = tid; i < B; i += 256) {
            int l = is_i32 ? raw[i] : raw[2 * i];
            g_lab[i] = l;
            atomicAdd(&s_hist[l & 63], 1);
            g_hp_bits[i] = 0;
            g_hn_bits[i] = 0x7F7FFFFF;
        }
        __syncthreads();
        if (tid < 64) g_cnt[tid] = s_hist[tid];
        return;
    }

    const int wslot = (blockIdx.x - 1) * 8 + (tid >> 5);   // 0..1023
    const int lane = tid & 31;
    const int row0 = wslot * 4;

    float4 va[4], vb[4];
    #pragma unroll
    for (int r = 0; r < 4; r++) {
        const float4* e = (const float4*)(E + (size_t)(row0 + r) * D);
        va[r] = e[2 * lane];
        vb[r] = e[2 * lane + 1];
    }
    #pragma unroll
    for (int r = 0; r < 4; r++) {
        uint4 ta, tb;
        ta.x = cvt_tf32(va[r].x); ta.y = cvt_tf32(va[r].y);
        ta.z = cvt_tf32(va[r].z); ta.w = cvt_tf32(va[r].w);
        tb.x = cvt_tf32(vb[r].x); tb.y = cvt_tf32(vb[r].y);
        tb.z = cvt_tf32(vb[r].z); tb.w = cvt_tf32(vb[r].w);

        float s = 0.f;
        const uint32_t* u = (const uint32_t*)&ta;
        const uint32_t* v = (const uint32_t*)&tb;
        #pragma unroll
        for (int q = 0; q < 4; q++) {
            float x = __uint_as_float(u[q]);
            float y = __uint_as_float(v[q]);
            s = fmaf(x, x, s);
            s = fmaf(y, y, s);
        }

        uint4* dst = (uint4*)(g_Etf + (size_t)(row0 + r) * D);
        dst[2 * lane] = ta;
        dst[2 * lane + 1] = tb;

        #pragma unroll
        for (int off = 16; off > 0; off >>= 1)
            s += __shfl_xor_sync(0xFFFFFFFFu, s, off);
        if (lane == 0) g_sq[row0 + r] = s;
    }
}

// ---------------------------------------------------------------------------
// k_gemm: R11 kernel verbatim — triangular tiles, 16 warps, warp tile 32x32,
//         TF32 m16n8k8, 3-buffer cp.async, dual-side epilogue. NOTHING fused.
// ---------------------------------------------------------------------------
__device__ __forceinline__ void issue_stage(uint32_t sbase, int i0, int j0,
                                            int s, int tid) {
    const int k0 = s * BK;
    #pragma unroll
    for (int m = 0; m < 8; m++) {
        int task = m * NTHREADS + tid;          // 0..4095
        int mat = task >> 11;                   // 0 = A, 1 = B
        int idx = task & 2047;
        int row = idx >> 4;
        int q = idx & 15;
        int grow = (mat == 0 ? i0 : j0) + row;
        const float* src = g_Etf + (size_t)grow * D + k0 + q * 4;
        uint32_t dst = sbase + mat * TILE_BYTES + row * STRIDE + q * 16;
        cp16(dst, src);
    }
}

__global__ __launch_bounds__(NTHREADS, 1) void k_gemm() {
    extern __shared__ char smem[];
    const int tid = threadIdx.x;
    const int lane = tid & 31;
    const int wid = tid >> 5;
    const int wm = wid >> 2;       // 0..3
    const int wn = wid & 3;        // 0..3

    int t = blockIdx.x;
    int bi = 0;
    while (t >= NTILE - bi) { t -= NTILE - bi; bi++; }
    const int bj = bi + t;
    const bool diag = (bi == bj);
    const int i0 = bi * 128;
    const int j0 = bj * 128;

    const uint32_t sb = (uint32_t)__cvta_generic_to_shared(smem);
    int* s_hp = (int*)(smem + SMEM_RED);
    int* s_hn = s_hp + 128;
    int* s_hp2 = s_hn + 128;
    int* s_hn2 = s_hp2 + 128;

    if (tid < 128) {
        s_hp[tid] = 0;  s_hn[tid] = 0x7F7FFFFF;
        s_hp2[tid] = 0; s_hn2[tid] = 0x7F7FFFFF;
    }

    float acc[2][4][4];
    #pragma unroll
    for (int a = 0; a < 2; a++)
        #pragma unroll
        for (int b = 0; b < 4; b++)
            #pragma unroll
            for (int c = 0; c < 4; c++)
                acc[a][b][c] = 0.f;

    const uint32_t aoff = (uint32_t)((wm * 32 + ((lane >> 3) & 1) * 8 + (lane & 7)) * STRIDE
                                     + (lane >> 4) * 16);
    const uint32_t boff = (uint32_t)((wn * 32 + ((lane >> 4) & 1) * 8 + (lane & 7)) * STRIDE
                                     + ((lane >> 3) & 1) * 16);

    issue_stage(sb, i0, j0, 0, tid);
    cp_commit();
    issue_stage(sb + STAGE_BYTES, i0, j0, 1, tid);
    cp_commit();

    #pragma unroll
    for (int s = 0; s < NSTAGE; s++) {
        if (s < NSTAGE - 1) cp_wait<1>(); else cp_wait<0>();
        __syncthreads();
        if (s + 2 < NSTAGE) {
            issue_stage(sb + ((s + 2) % NBUF) * STAGE_BYTES, i0, j0, s + 2, tid);
            cp_commit();
        }

        const uint32_t Abase = sb + (s % NBUF) * STAGE_BYTES + aoff;
        const uint32_t Bbase = sb + (s % NBUF) * STAGE_BYTES + TILE_BYTES + boff;

        #pragma unroll
        for (int kk = 0; kk < 2; kk++) {
            #pragma unroll
            for (int h = 0; h < 4; h++) {
                const uint32_t kb = (uint32_t)(kk * 128 + h * 32);
                uint32_t a[2][4], b[2][4];
                #pragma unroll
                for (int mi = 0; mi < 2; mi++)
                    ldm4(a[mi], Abase + mi * 16 * STRIDE + kb);
                #pragma unroll
                for (int p = 0; p < 2; p++)
                    ldm4(b[p], Bbase + p * 16 * STRIDE + kb);
                #pragma unroll
                for (int mi = 0; mi < 2; mi++) {
                    #pragma unroll
                    for (int ni = 0; ni < 4; ni++) {
                        const int p = ni >> 1, o = (ni & 1) * 2;
                        mma_tf32(acc[mi][ni], a[mi], b[p][o], b[p][o + 1]);
                    }
                }
            }
        }
    }
    __syncthreads();

    // ---- epilogue ----
    int lj[8], gjs[8];
    float sqj[8];
    #pragma unroll
    for (int idx = 0; idx < 8; idx++) {
        const int ni = idx >> 1, c = idx & 1;
        const int gj = j0 + wn * 32 + ni * 8 + (lane & 3) * 2 + c;
        gjs[idx] = gj;
        lj[idx] = g_lab[gj];
        sqj[idx] = g_sq[gj];
    }

    float chp[8], chn[8];
    #pragma unroll
    for (int idx = 0; idx < 8; idx++) { chp[idx] = 0.f; chn[idx] = 3.4e38f; }

    #pragma unroll
    for (int mi = 0; mi < 2; mi++) {
        #pragma unroll
        for (int h = 0; h < 2; h++) {
            const int rloc = wm * 32 + mi * 16 + h * 8 + (lane >> 2);
            const int gi = i0 + rloc;
            const int li = g_lab[gi];
            const float sqi = g_sq[gi];
            float hp = 0.f, hn = 3.4e38f;
            #pragma unroll
            for (int ni = 0; ni < 4; ni++) {
                #pragma unroll
                for (int c = 0; c < 2; c++) {
                    const int idx = ni * 2 + c;
                    float d2 = fmaf(-2.f, acc[mi][ni][h * 2 + c], sqi + sqj[idx]);
                    const bool same = (lj[idx] == li);
                    const bool self = (gjs[idx] == gi);
                    if (same) {
                        if (!self) {
                            hp = fmaxf(hp, d2);
                            chp[idx] = fmaxf(chp[idx], d2);
                        }
                    } else {
                        hn = fminf(hn, d2);
                        chn[idx] = fminf(chn[idx], d2);
                    }
                }
            }
            hp = fmaxf(hp, __shfl_xor_sync(0xFFFFFFFFu, hp, 1));
            hn = fminf(hn, __shfl_xor_sync(0xFFFFFFFFu, hn, 1));
            hp = fmaxf(hp, __shfl_xor_sync(0xFFFFFFFFu, hp, 2));
            hn = fminf(hn, __shfl_xor_sync(0xFFFFFFFFu, hn, 2));
            if ((lane & 3) == 0) {
                atomicMax(&s_hp[rloc], __float_as_int(hp));
                atomicMin(&s_hn[rloc], __float_as_int(hn));
            }
        }
    }

    if (!diag) {
        #pragma unroll
        for (int idx = 0; idx < 8; idx++) {
            float vp = chp[idx], vn = chn[idx];
            #pragma unroll
            for (int m = 4; m < 32; m <<= 1) {
                vp = fmaxf(vp, __shfl_xor_sync(0xFFFFFFFFu, vp, m));
                vn = fminf(vn, __shfl_xor_sync(0xFFFFFFFFu, vn, m));
            }
            if ((lane >> 2) == 0) {
                const int ni = idx >> 1, c = idx & 1;
                const int cloc = wn * 32 + ni * 8 + (lane & 3) * 2 + c;
                atomicMax(&s_hp2[cloc], __float_as_int(vp));
                atomicMin(&s_hn2[cloc], __float_as_int(vn));
            }
        }
    }

    __syncthreads();
    if (tid < 128) {
        atomicMax(&g_hp_bits[i0 + tid], s_hp[tid]);
        atomicMin(&g_hn_bits[i0 + tid], s_hn[tid]);
        if (!diag) {
            atomicMax(&g_hp_bits[j0 + tid], s_hp2[tid]);
            atomicMin(&g_hn_bits[j0 + tid], s_hn2[tid]);
        }
    }
}

// ---------------------------------------------------------------------------
// k_final: partial blocks -> atomics; last block writes out.
// ---------------------------------------------------------------------------
__global__ __launch_bounds__(256) void k_final(float* __restrict__ out) {
    const int i = blockIdx.x * 256 + threadIdx.x;
    const int tid = threadIdx.x;
    float sum = 0.f, cnt = 0.f;
    const int c = g_cnt[g_lab[i] & 63];
    if (c >= 2 && c <= B - 1) {
        float hp = sqrtf(fmaxf(__int_as_float(g_hp_bits[i]), 0.f));
        float hn = sqrtf(fmaxf(__int_as_float(g_hn_bits[i]), 0.f));
        float l = hp - hn + MARGIN;
        if (l > 0.f) sum = l;
        cnt = 1.f;
    }
    #pragma unroll
    for (int m = 16; m > 0; m >>= 1) {
        sum += __shfl_xor_sync(0xFFFFFFFFu, sum, m);
        cnt += __shfl_xor_sync(0xFFFFFFFFu, cnt, m);
    }
    __shared__ float ss[8], sc[8];
    __shared__ bool is_last;
    if ((tid & 31) == 0) { ss[tid >> 5] = sum; sc[tid >> 5] = cnt; }
    __syncthreads();
    if (tid == 0) {
        float S = 0.f, C = 0.f;
        #pragma unroll
        for (int w = 0; w < 8; w++) { S += ss[w]; C += sc[w]; }
        atomicAdd(&g_sum, S);
        atomicAdd(&g_vcnt, C);
        __threadfence();
        unsigned int n = atomicAdd(&g_done, 1u);
        is_last = (n == gridDim.x - 1);
    }
    __syncthreads();
    if (is_last && tid == 0) {
        float cfin = *((volatile float*)&g_vcnt);
        float sfin = *((volatile float*)&g_sum);
        out[0] = (cfin > 0.f) ? (sfin / cfin) : 0.f;
    }
}

// ---------------------------------------------------------------------------
extern "C" void kernel_launch(void* const* d_in, const int* in_sizes, int n_in,
                              void* d_out, int out_size) {
    const float* E = (const float*)d_in[0];
    const int* labels_raw = (const int*)d_in[1];
    float* out = (float*)d_out;

    static bool attr_set = false;
    if (!attr_set) {
        cudaFuncSetAttribute(k_gemm, cudaFuncAttributeMaxDynamicSharedMemorySize,
                             SMEM_TOTAL);
        attr_set = true;
    }

    k_prep<<<129, 256>>>(E, labels_raw);
    k_gemm<<<NTRI, NTHREADS, SMEM_TOTAL>>>();
    k_final<<<B / 256, 256>>>(out);
}